// round 2
// baseline (speedup 1.0000x reference)
#include <cuda_runtime.h>
#include <cuda_bf16.h>
#include <math.h>

// Problem constants
#define B_   8
#define C_   256
#define H_   64
#define W_   64
#define HW_  4096
#define CO_  256
#define OCF_ 18   // 2*K offset channels
#define K_   9

// Scratch (device globals: no allocation allowed)
__device__ float g_offset[B_ * OCF_ * HW_];        // [B,18,H,W]
__device__ float g_wt[K_ * C_ * CO_];              // [k][c][o] transposed deform weights
__device__ float g_y[B_ * CO_ * HW_];              // pre-attention output

// ---------------------------------------------------------------------------
// Kernel 0: transpose deform_w [o][c][k] -> g_wt [k][c][o]
// ---------------------------------------------------------------------------
__global__ void __launch_bounds__(256) wt_transpose_kernel(const float* __restrict__ dw) {
    int e = blockIdx.x * 256 + threadIdx.x;        // 0 .. 589823
    int o = e & 255;
    int c = (e >> 8) & 255;
    int k = e >> 16;
    g_wt[e] = dw[((size_t)o * C_ + c) * K_ + k];
}

// ---------------------------------------------------------------------------
// Kernel 1: offset conv (3x3, pad 1, 256 -> 18 channels)
// One thread per output spatial position, all 18 channels in registers.
// Weights staged per 64-c chunk in smem (padded 18->20 for float4 reads).
// ---------------------------------------------------------------------------
__global__ void __launch_bounds__(256) offset_conv_kernel(const float* __restrict__ x,
                                                          const float* __restrict__ ow) {
    __shared__ float w_s[64 * 180];                // [cc][tap][20]
    int tid = threadIdx.x;
    int gid = blockIdx.x * 256 + tid;              // 0 .. 32767
    int b   = gid >> 12;
    int rem = gid & 4095;
    int ho  = rem >> 6, wo = rem & 63;

    float acc[20];
#pragma unroll
    for (int i = 0; i < 20; i++) acc[i] = 0.f;

    // Precompute tap indices with zero-padding (-1 = padded)
    int xoff[9];
#pragma unroll
    for (int kh = 0; kh < 3; kh++)
#pragma unroll
        for (int kw = 0; kw < 3; kw++) {
            int y = ho - 1 + kh, xx = wo - 1 + kw;
            bool v = ((unsigned)y < 64u) && ((unsigned)xx < 64u);
            xoff[kh * 3 + kw] = v ? (y * 64 + xx) : -1;
        }

    const float* xb = x + (size_t)b * C_ * HW_;

    for (int c0 = 0; c0 < C_; c0 += 64) {
        __syncthreads();
        for (int i = tid; i < 64 * 180; i += 256) {
            int cc = i / 180, r = i % 180, tap = r / 20, ch = r % 20;
            w_s[i] = (ch < 18) ? ow[((size_t)ch * C_ + (c0 + cc)) * K_ + tap] : 0.f;
        }
        __syncthreads();

        for (int cc = 0; cc < 64; cc++) {
            const float* xp = xb + (size_t)(c0 + cc) * HW_;
            float xv[9];
#pragma unroll
            for (int t = 0; t < 9; t++) xv[t] = (xoff[t] >= 0) ? xp[xoff[t]] : 0.f;

            const float* wb = &w_s[cc * 180];
#pragma unroll
            for (int t = 0; t < 9; t++) {
                float v = xv[t];
#pragma unroll
                for (int q = 0; q < 5; q++) {
                    float4 w4 = *(const float4*)(wb + t * 20 + q * 4);
                    acc[q * 4 + 0] = fmaf(v, w4.x, acc[q * 4 + 0]);
                    acc[q * 4 + 1] = fmaf(v, w4.y, acc[q * 4 + 1]);
                    acc[q * 4 + 2] = fmaf(v, w4.z, acc[q * 4 + 2]);
                    acc[q * 4 + 3] = fmaf(v, w4.w, acc[q * 4 + 3]);
                }
            }
        }
    }
#pragma unroll
    for (int ch = 0; ch < 18; ch++)
        g_offset[((size_t)b * OCF_ + ch) * HW_ + rem] = acc[ch];
}

// ---------------------------------------------------------------------------
// Kernel 2: deformable conv as implicit GEMM.
// Block = (b, ho, half-row of 32 positions). Threads = 256 output channels.
// Per (k, c-chunk of 32): bilinear-gather patch tile [32c x 32p] into smem,
// stage weight tile [32c x 256o] (coalesced from g_wt), rank-32 update.
// ---------------------------------------------------------------------------
__global__ void __launch_bounds__(256) deform_kernel(const float* __restrict__ x) {
    __shared__ float s_wgt[9][32][4];
    __shared__ int   s_idx[9][32][4];
    __shared__ float smem_big[8192 + 1024];        // w_s (8192) | patch_s (1024); reused for transpose
    float* w_s = smem_big;
    float (*patch_s)[32] = (float(*)[32])(smem_big + 8192);

    int tid  = threadIdx.x;
    int blk  = blockIdx.x;                          // 0..1023
    int half = blk & 1;
    int ho   = (blk >> 1) & 63;
    int b    = blk >> 7;
    int wo0  = half * 32;

    // --- sampling precompute: 9 taps x 32 positions -> 4 corners each ---
    for (int item = tid; item < 288; item += 256) {
        int k = item >> 5, p = item & 31;
        int wo = wo0 + p;
        const float* offp = g_offset + (size_t)b * OCF_ * HW_ + ho * 64 + wo;
        float dy = offp[(size_t)(2 * k) * HW_];
        float dx = offp[(size_t)(2 * k + 1) * HW_];
        float sy = (float)(ho - 1 + k / 3) + dy;
        float sx = (float)(wo - 1 + k % 3) + dx;
        float y0f = floorf(sy), x0f = floorf(sx);
        float ly = sy - y0f, lx = sx - x0f;
        int y0 = (int)y0f, x0 = (int)x0f;
#pragma unroll
        for (int j = 0; j < 4; j++) {
            int yc = y0 + (j >> 1), xc = x0 + (j & 1);
            float wy = (j >> 1) ? ly : 1.f - ly;
            float wx = (j & 1)  ? lx : 1.f - lx;
            bool valid = ((unsigned)yc < 64u) && ((unsigned)xc < 64u);
            s_wgt[k][p][j] = valid ? (wy * wx) : 0.f;
            int ycc = min(max(yc, 0), 63), xcc = min(max(xc, 0), 63);
            s_idx[k][p][j] = ycc * 64 + xcc;
        }
    }

    float acc[32];
#pragma unroll
    for (int i = 0; i < 32; i++) acc[i] = 0.f;

    const float* xb0 = x + (size_t)b * C_ * HW_;

    for (int k = 0; k < 9; k++) {
        for (int c0 = 0; c0 < C_; c0 += 32) {
            __syncthreads();  // also covers sampling precompute on first iter
            // stage weights [32c][256o], coalesced float4
            const float4* wt = (const float4*)(g_wt + ((size_t)k * C_ + c0) * CO_);
            float4* wd = (float4*)w_s;
#pragma unroll
            for (int i = 0; i < 8; i++) wd[tid + i * 256] = wt[tid + i * 256];
            // gather patch tile [32c][32p]
#pragma unroll
            for (int i = 0; i < 4; i++) {
                int e = tid + i * 256;
                int cc = e >> 5, p = e & 31;
                const float* xp = xb0 + (size_t)(c0 + cc) * HW_;
                const float* wg = s_wgt[k][p];
                const int*   ig = s_idx[k][p];
                float v = wg[0] * xp[ig[0]] + wg[1] * xp[ig[1]]
                        + wg[2] * xp[ig[2]] + wg[3] * xp[ig[3]];
                patch_s[cc][p] = v;
            }
            __syncthreads();
            // rank-32 outer-product update
#pragma unroll 4
            for (int cc = 0; cc < 32; cc++) {
                float wv = w_s[cc * 256 + tid];
                const float4* pp = (const float4*)patch_s[cc];
#pragma unroll
                for (int q = 0; q < 8; q++) {
                    float4 v = pp[q];
                    acc[q * 4 + 0] = fmaf(wv, v.x, acc[q * 4 + 0]);
                    acc[q * 4 + 1] = fmaf(wv, v.y, acc[q * 4 + 1]);
                    acc[q * 4 + 2] = fmaf(wv, v.z, acc[q * 4 + 2]);
                    acc[q * 4 + 3] = fmaf(wv, v.w, acc[q * 4 + 3]);
                }
            }
        }
    }

    // transpose in smem for coalesced stores
    __syncthreads();
    float* tb = smem_big;                           // 256*33 = 8448 floats (fits 9216)
#pragma unroll
    for (int p = 0; p < 32; p++) tb[tid * 33 + p] = acc[p];
    __syncthreads();
    int lane = tid & 31, warp = tid >> 5;
    // Each thread reads back 32 elements: full 256-o coverage (fixes R1 bug
    // where only o<64 was written). Consecutive lanes -> consecutive gmem.
#pragma unroll
    for (int r = 0; r < 32; r++) {
        int o = warp * 32 + r;
        g_y[((size_t)(b * CO_ + o)) * HW_ + ho * 64 + wo0 + lane] = tb[o * 33 + lane];
    }
}

// ---------------------------------------------------------------------------
// Kernel 3: channel attention: attn = sigmoid(mean + std(ddof=1)), out = y*attn
// One block per (b, o); y tile kept in registers for the scale pass.
// ---------------------------------------------------------------------------
__global__ void __launch_bounds__(256) attn_kernel(float* __restrict__ out) {
    int bo = blockIdx.x;                            // 0..2047
    const float4* yp = (const float4*)(g_y + (size_t)bo * HW_);
    int tid = threadIdx.x;

    float s = 0.f, s2 = 0.f;
    float4 v[4];
#pragma unroll
    for (int i = 0; i < 4; i++) {
        v[i] = yp[tid + i * 256];
        s  += v[i].x + v[i].y + v[i].z + v[i].w;
        s2 += v[i].x * v[i].x + v[i].y * v[i].y + v[i].z * v[i].z + v[i].w * v[i].w;
    }
#pragma unroll
    for (int off = 16; off; off >>= 1) {
        s  += __shfl_down_sync(0xffffffffu, s,  off);
        s2 += __shfl_down_sync(0xffffffffu, s2, off);
    }
    __shared__ float rs[8], rs2[8];
    __shared__ float sa;
    int lane = tid & 31, w = tid >> 5;
    if (lane == 0) { rs[w] = s; rs2[w] = s2; }
    __syncthreads();
    if (tid == 0) {
        float S = 0.f, S2 = 0.f;
#pragma unroll
        for (int i = 0; i < 8; i++) { S += rs[i]; S2 += rs2[i]; }
        float mean = S * (1.f / 4096.f);
        float var  = (S2 - S * S * (1.f / 4096.f)) * (1.f / 4095.f);
        float sd   = sqrtf(fmaxf(var, 0.f));
        sa = 1.f / (1.f + expf(-(mean + sd)));
    }
    __syncthreads();
    float a = sa;
    float4* op = (float4*)(out + (size_t)bo * HW_);
#pragma unroll
    for (int i = 0; i < 4; i++) {
        float4 u = v[i];
        u.x *= a; u.y *= a; u.z *= a; u.w *= a;
        op[tid + i * 256] = u;
    }
}

// ---------------------------------------------------------------------------
extern "C" void kernel_launch(void* const* d_in, const int* in_sizes, int n_in,
                              void* d_out, int out_size) {
    const float* x  = (const float*)d_in[0];   // [8,256,64,64]
    const float* ow = (const float*)d_in[1];   // [18,256,3,3]
    const float* dw = (const float*)d_in[2];   // [256,256,3,3]
    float* out = (float*)d_out;                // [8,256,64,64]

    wt_transpose_kernel<<<(K_ * C_ * CO_) / 256, 256>>>(dw);
    offset_conv_kernel<<<(B_ * HW_) / 256, 256>>>(x, ow);
    deform_kernel<<<B_ * 64 * 2, 256>>>(x);
    attn_kernel<<<B_ * CO_, 256>>>(out);
}

// round 4
// speedup vs baseline: 2.3778x; 2.3778x over previous
#include <cuda_runtime.h>
#include <cuda_bf16.h>
#include <math.h>
#include <stdint.h>

// Problem constants
#define B_   8
#define C_   256
#define H_   64
#define W_   64
#define HW_  4096
#define CO_  256
#define OCF_ 18
#define K_   9

// ---------------------------------------------------------------------------
// Device-global scratch
// ---------------------------------------------------------------------------
__device__ float g_offset[B_ * OCF_ * HW_];                 // [B,18,H,W]
__device__ __nv_bfloat16 g_wtb_hi[K_ * CO_ * C_];           // [k][o][c] bf16 hi
__device__ __nv_bfloat16 g_wtb_lo[K_ * CO_ * C_];           // [k][o][c] bf16 lo
__device__ float g_y[B_ * CO_ * HW_];                       // pre-attention output

// ---------------------------------------------------------------------------
// Helpers (baseline PTX only: ldmatrix + mma.sync, sm_80+; compiles on sm_103)
// ---------------------------------------------------------------------------
__device__ __forceinline__ uint32_t smem_u32(const void* p) {
    uint32_t a;
    asm("{ .reg .u64 t; cvta.to.shared.u64 t, %1; cvt.u32.u64 %0, t; }" : "=r"(a) : "l"(p));
    return a;
}
__device__ __forceinline__ uint32_t swz(uint32_t b) { return b ^ ((b >> 3) & 0x70); }

__device__ __forceinline__ void ldsm4(uint32_t* r, uint32_t addr) {
    asm volatile("ldmatrix.sync.aligned.m8n8.x4.shared.b16 {%0,%1,%2,%3}, [%4];"
        : "=r"(r[0]), "=r"(r[1]), "=r"(r[2]), "=r"(r[3]) : "r"(addr));
}
__device__ __forceinline__ void mma16816(float* d, const uint32_t* a, const uint32_t* b) {
    asm volatile("mma.sync.aligned.m16n8k16.row.col.f32.bf16.bf16.f32 "
        "{%0,%1,%2,%3}, {%4,%5,%6,%7}, {%8,%9}, {%0,%1,%2,%3};"
        : "+f"(d[0]), "+f"(d[1]), "+f"(d[2]), "+f"(d[3])
        : "r"(a[0]), "r"(a[1]), "r"(a[2]), "r"(a[3]), "r"(b[0]), "r"(b[1]));
}

// ---------------------------------------------------------------------------
// SMEM layout for deform kernel (dynamic)
//   P = patches [128 p][64 c] bf16 (SW128 swizzled rows of 128B)
//   W = weights [256 o][64 c] bf16 (SW128 swizzled rows of 128B)
// ---------------------------------------------------------------------------
#define OFF_P_HI   0
#define OFF_P_LO   16384
#define OFF_W_HI   32768
#define OFF_W_LO   65536
#define OFF_SAMP_W 98304          // float[128][4]
#define OFF_SAMP_I 100352         // int[128][4]
#define SMEM_TOTAL 102400

// ---------------------------------------------------------------------------
// Kernel 0: weight prep — dw [o][c][k] fp32 -> [k][o][c] bf16 hi/lo
// ---------------------------------------------------------------------------
__global__ void __launch_bounds__(256) wt_prep_kernel(const float* __restrict__ dw) {
    int e = blockIdx.x * 256 + threadIdx.x;
    int c = e & 255;
    int o = (e >> 8) & 255;
    int k = e >> 16;
    float v = dw[((size_t)o * C_ + c) * K_ + k];
    __nv_bfloat16 h = __float2bfloat16(v);
    g_wtb_hi[e] = h;
    g_wtb_lo[e] = __float2bfloat16(v - __bfloat162float(h));
}

// ---------------------------------------------------------------------------
// Kernel 1: offset conv (3x3, pad 1, 256 -> 18 channels)
// ---------------------------------------------------------------------------
__global__ void __launch_bounds__(256) offset_conv_kernel(const float* __restrict__ x,
                                                          const float* __restrict__ ow) {
    __shared__ float w_s[64 * 180];
    int tid = threadIdx.x;
    int gid = blockIdx.x * 256 + tid;
    int b   = gid >> 12;
    int rem = gid & 4095;
    int ho  = rem >> 6, wo = rem & 63;

    float acc[20];
#pragma unroll
    for (int i = 0; i < 20; i++) acc[i] = 0.f;

    int xoff[9];
#pragma unroll
    for (int kh = 0; kh < 3; kh++)
#pragma unroll
        for (int kw = 0; kw < 3; kw++) {
            int y = ho - 1 + kh, xx = wo - 1 + kw;
            bool v = ((unsigned)y < 64u) && ((unsigned)xx < 64u);
            xoff[kh * 3 + kw] = v ? (y * 64 + xx) : -1;
        }

    const float* xb = x + (size_t)b * C_ * HW_;

    for (int c0 = 0; c0 < C_; c0 += 64) {
        __syncthreads();
        for (int i = tid; i < 64 * 180; i += 256) {
            int cc = i / 180, r = i % 180, tap = r / 20, ch = r % 20;
            w_s[i] = (ch < 18) ? ow[((size_t)ch * C_ + (c0 + cc)) * K_ + tap] : 0.f;
        }
        __syncthreads();

        for (int cc = 0; cc < 64; cc++) {
            const float* xp = xb + (size_t)(c0 + cc) * HW_;
            float xv[9];
#pragma unroll
            for (int t = 0; t < 9; t++) xv[t] = (xoff[t] >= 0) ? xp[xoff[t]] : 0.f;

            const float* wb = &w_s[cc * 180];
#pragma unroll
            for (int t = 0; t < 9; t++) {
                float v = xv[t];
#pragma unroll
                for (int q = 0; q < 5; q++) {
                    float4 w4 = *(const float4*)(wb + t * 20 + q * 4);
                    acc[q * 4 + 0] = fmaf(v, w4.x, acc[q * 4 + 0]);
                    acc[q * 4 + 1] = fmaf(v, w4.y, acc[q * 4 + 1]);
                    acc[q * 4 + 2] = fmaf(v, w4.z, acc[q * 4 + 2]);
                    acc[q * 4 + 3] = fmaf(v, w4.w, acc[q * 4 + 3]);
                }
            }
        }
    }
#pragma unroll
    for (int ch = 0; ch < 18; ch++)
        g_offset[((size_t)b * OCF_ + ch) * HW_ + rem] = acc[ch];
}

// ---------------------------------------------------------------------------
// Kernel 2: deformable conv via warp-level mma.sync (bf16 x3 split).
// CTA = (b, row-pair): D[256 o][128 p], K = 9 taps x 4 c-chunks of 64.
// 8 warps = 4 (o) x 2 (p); warp tile 64 o x 64 p; acc 128 regs/thread.
// ---------------------------------------------------------------------------
__global__ void __launch_bounds__(256, 1) deform_mma_kernel(const float* __restrict__ x) {
    extern __shared__ char smem[];
    uint32_t sb = smem_u32(smem);
    int tid = threadIdx.x, wid = tid >> 5, lane = tid & 31;
    int blk = blockIdx.x;                 // 0..255
    int b   = blk >> 5;
    int rp  = blk & 31;
    int ho0 = rp * 2;
    int pos0 = ho0 * 64;
    int wo = wid >> 1;                    // o quarter (0..3) -> 64 outs
    int wp = wid & 1;                     // p half (0..1)    -> 64 pos

    float* samp_w = (float*)(smem + OFF_SAMP_W);
    int*   samp_i = (int*)(smem + OFF_SAMP_I);
    const float* xb = x + (size_t)b * C_ * HW_;

    float acc[4][8][4];
#pragma unroll
    for (int i = 0; i < 4; i++)
#pragma unroll
        for (int j = 0; j < 8; j++)
#pragma unroll
            for (int q = 0; q < 4; q++) acc[i][j][q] = 0.f;

    // ldmatrix lane geometry (constant per thread)
    int mat = lane >> 3, mr = lane & 7;

#pragma unroll 1
    for (int chunk = 0; chunk < 36; chunk++) {
        int k  = chunk >> 2;
        int c0 = (chunk & 3) << 6;

        // --- sampling precompute (per tap) ---
        if (c0 == 0 && tid < 128) {
            int p = tid;
            int ho = ho0 + (p >> 6), wo2 = p & 63;
            const float* offp = g_offset + (size_t)b * OCF_ * HW_ + ho * 64 + wo2;
            float dy = offp[(size_t)(2 * k) * HW_];
            float dx = offp[(size_t)(2 * k + 1) * HW_];
            float sy = (float)(ho - 1 + k / 3) + dy;
            float sx = (float)(wo2 - 1 + k % 3) + dx;
            float y0f = floorf(sy), x0f = floorf(sx);
            float ly = sy - y0f, lx = sx - x0f;
            int y0 = (int)y0f, x0 = (int)x0f;
#pragma unroll
            for (int j = 0; j < 4; j++) {
                int yc = y0 + (j >> 1), xc = x0 + (j & 1);
                float wy = (j >> 1) ? ly : 1.f - ly;
                float wx = (j & 1)  ? lx : 1.f - lx;
                bool v = ((unsigned)yc < 64u) && ((unsigned)xc < 64u);
                samp_w[p * 4 + j] = v ? wy * wx : 0.f;
                samp_i[p * 4 + j] = min(max(yc, 0), 63) * 64 + min(max(xc, 0), 63);
            }
        }
        __syncthreads();   // samp visible; prev chunk's ldmatrix reads complete

        // --- stage weights: [256 o][64 c] hi/lo ---
        {
            const char* wh = (const char*)(g_wtb_hi + (size_t)k * CO_ * C_ + c0);
            const char* wl = (const char*)(g_wtb_lo + (size_t)k * CO_ * C_ + c0);
#pragma unroll
            for (int i = 0; i < 8; i++) {
                int e = tid + i * 256;          // 0..2047
                int o = e >> 3, q = e & 7;
                uint32_t sw = swz((uint32_t)(o * 128 + q * 16));
                *(uint4*)(smem + OFF_W_HI + sw) = *(const uint4*)(wh + (size_t)o * 512 + q * 16);
                *(uint4*)(smem + OFF_W_LO + sw) = *(const uint4*)(wl + (size_t)o * 512 + q * 16);
            }
        }

        // --- gather patches: [128 p][64 c] hi/lo ---
        {
#pragma unroll
            for (int g = 0; g < 4; g++) {
                int e  = g * 256 + tid;         // 0..1023
                int p  = e & 127;               // lanes vary p -> coalesced-ish LDG
                int c8 = e >> 7;                // channel group of 8
                const float4 wv = *(const float4*)(samp_w + p * 4);
                const int4   iv = *(const int4*)(samp_i + p * 4);
                uint32_t hp[4], lp[4];
#pragma unroll
                for (int j = 0; j < 4; j++) {
                    const float* xp0 = xb + (size_t)(c0 + c8 * 8 + j * 2) * HW_;
                    const float* xp1 = xp0 + HW_;
                    float v0 = wv.x * xp0[iv.x] + wv.y * xp0[iv.y]
                             + wv.z * xp0[iv.z] + wv.w * xp0[iv.w];
                    float v1 = wv.x * xp1[iv.x] + wv.y * xp1[iv.y]
                             + wv.z * xp1[iv.z] + wv.w * xp1[iv.w];
                    __nv_bfloat16 h0 = __float2bfloat16(v0);
                    __nv_bfloat16 h1 = __float2bfloat16(v1);
                    __nv_bfloat16 l0 = __float2bfloat16(v0 - __bfloat162float(h0));
                    __nv_bfloat16 l1 = __float2bfloat16(v1 - __bfloat162float(h1));
                    __nv_bfloat162 h2; h2.x = h0; h2.y = h1;
                    __nv_bfloat162 l2; l2.x = l0; l2.y = l1;
                    hp[j] = *(uint32_t*)&h2;
                    lp[j] = *(uint32_t*)&l2;
                }
                uint32_t sw = swz((uint32_t)(p * 128 + c8 * 16));
                *(uint4*)(smem + OFF_P_HI + sw) = *(uint4*)hp;
                *(uint4*)(smem + OFF_P_LO + sw) = *(uint4*)lp;
            }
        }

        __syncthreads();   // stage published

        // --- mma: 4 ksteps x (4 o-tiles x 8 p-tiles) x 3 splits ---
#pragma unroll
        for (int ks = 0; ks < 4; ks++) {
            uint32_t ah[4][4], al[4][4];
#pragma unroll
            for (int mt = 0; mt < 4; mt++) {
                // A (weights) m16k16: mats {m0k0, m8k0, m0k8, m8k8}
                uint32_t byte = (uint32_t)((wo * 64 + mt * 16 + (mat & 1) * 8 + mr) * 128
                                           + ks * 32 + (mat >> 1) * 16);
                uint32_t adr = swz(byte);
                ldsm4(ah[mt], sb + OFF_W_HI + adr);
                ldsm4(al[mt], sb + OFF_W_LO + adr);
            }
#pragma unroll
            for (int np = 0; np < 4; np++) {
                // B (patches) covers 2 n-tiles (16 p) x k16:
                // mats {p0k0, p0k8, p8k0, p8k8} -> regs {b0,b1,b2,b3}
                uint32_t byte = (uint32_t)((wp * 64 + np * 16 + (mat >> 1) * 8 + mr) * 128
                                           + ks * 32 + (mat & 1) * 16);
                uint32_t adr = swz(byte);
                uint32_t bh[4], bl[4];
                ldsm4(bh, sb + OFF_P_HI + adr);
                ldsm4(bl, sb + OFF_P_LO + adr);
#pragma unroll
                for (int mt = 0; mt < 4; mt++) {
                    mma16816(acc[mt][2 * np],     ah[mt], bh);       // hh
                    mma16816(acc[mt][2 * np + 1], ah[mt], bh + 2);
                    mma16816(acc[mt][2 * np],     ah[mt], bl);       // h*l
                    mma16816(acc[mt][2 * np + 1], ah[mt], bl + 2);
                    mma16816(acc[mt][2 * np],     al[mt], bh);       // l*h
                    mma16816(acc[mt][2 * np + 1], al[mt], bh + 2);
                }
            }
        }
    }

    // --- epilogue: D frag (m=o, n=p) -> g_y[b][o][pos0+p], STG.64 contiguous p ---
    int l4 = lane >> 2, l2 = (lane & 3) * 2;
#pragma unroll
    for (int mt = 0; mt < 4; mt++) {
#pragma unroll
        for (int nt = 0; nt < 8; nt++) {
            int o = wo * 64 + mt * 16 + l4;
            int p = wp * 64 + nt * 8 + l2;
            float* dst = g_y + ((size_t)(b * CO_ + o)) * HW_ + pos0 + p;
            float2 v01 = make_float2(acc[mt][nt][0], acc[mt][nt][1]);
            float2 v23 = make_float2(acc[mt][nt][2], acc[mt][nt][3]);
            *(float2*)dst = v01;
            *(float2*)(dst + (size_t)8 * HW_) = v23;
        }
    }
}

// ---------------------------------------------------------------------------
// Kernel 3: channel attention
// ---------------------------------------------------------------------------
__global__ void __launch_bounds__(256) attn_kernel(float* __restrict__ out) {
    int bo = blockIdx.x;
    const float4* yp = (const float4*)(g_y + (size_t)bo * HW_);
    int tid = threadIdx.x;

    float s = 0.f, s2 = 0.f;
    float4 v[4];
#pragma unroll
    for (int i = 0; i < 4; i++) {
        v[i] = yp[tid + i * 256];
        s  += v[i].x + v[i].y + v[i].z + v[i].w;
        s2 += v[i].x * v[i].x + v[i].y * v[i].y + v[i].z * v[i].z + v[i].w * v[i].w;
    }
#pragma unroll
    for (int off = 16; off; off >>= 1) {
        s  += __shfl_down_sync(0xffffffffu, s,  off);
        s2 += __shfl_down_sync(0xffffffffu, s2, off);
    }
    __shared__ float rs[8], rs2[8];
    __shared__ float sa;
    int lane = tid & 31, w = tid >> 5;
    if (lane == 0) { rs[w] = s; rs2[w] = s2; }
    __syncthreads();
    if (tid == 0) {
        float S = 0.f, S2 = 0.f;
#pragma unroll
        for (int i = 0; i < 8; i++) { S += rs[i]; S2 += rs2[i]; }
        float mean = S * (1.f / 4096.f);
        float var  = (S2 - S * S * (1.f / 4096.f)) * (1.f / 4095.f);
        float sd   = sqrtf(fmaxf(var, 0.f));
        sa = 1.f / (1.f + expf(-(mean + sd)));
    }
    __syncthreads();
    float a = sa;
    float4* op = (float4*)(out + (size_t)bo * HW_);
#pragma unroll
    for (int i = 0; i < 4; i++) {
        float4 u = v[i];
        u.x *= a; u.y *= a; u.z *= a; u.w *= a;
        op[tid + i * 256] = u;
    }
}

// ---------------------------------------------------------------------------
extern "C" void kernel_launch(void* const* d_in, const int* in_sizes, int n_in,
                              void* d_out, int out_size) {
    const float* x  = (const float*)d_in[0];   // [8,256,64,64]
    const float* ow = (const float*)d_in[1];   // [18,256,3,3]
    const float* dw = (const float*)d_in[2];   // [256,256,3,3]
    float* out = (float*)d_out;                // [8,256,64,64]

    cudaFuncSetAttribute(deform_mma_kernel,
                         cudaFuncAttributeMaxDynamicSharedMemorySize, SMEM_TOTAL);

    wt_prep_kernel<<<(K_ * CO_ * C_) / 256, 256>>>(dw);
    offset_conv_kernel<<<(B_ * HW_) / 256, 256>>>(x, ow);
    deform_mma_kernel<<<B_ * 32, 256, SMEM_TOTAL>>>(x);
    attn_kernel<<<B_ * CO_, 256>>>(out);
}

// round 5
// speedup vs baseline: 2.6294x; 1.1058x over previous
#include <cuda_runtime.h>
#include <cuda_bf16.h>
#include <math.h>
#include <stdint.h>

// Problem constants
#define B_   8
#define C_   256
#define H_   64
#define W_   64
#define HW_  4096
#define CO_  256
#define OCF_ 18
#define K_   9

// ---------------------------------------------------------------------------
// Device-global scratch
// ---------------------------------------------------------------------------
__device__ float g_offset[B_ * OCF_ * HW_];                 // [B,18,H,W]
__device__ __nv_bfloat16 g_wtb_hi[K_ * CO_ * C_];           // [k][o][c] bf16 hi
__device__ __nv_bfloat16 g_wtb_lo[K_ * CO_ * C_];           // [k][o][c] bf16 lo
__device__ float g_y[B_ * CO_ * HW_];                       // pre-attention output

// ---------------------------------------------------------------------------
// Helpers (baseline PTX only: ldmatrix/mma.sync/cp.async are sm_80+)
// ---------------------------------------------------------------------------
__device__ __forceinline__ uint32_t smem_u32(const void* p) {
    uint32_t a;
    asm("{ .reg .u64 t; cvta.to.shared.u64 t, %1; cvt.u32.u64 %0, t; }" : "=r"(a) : "l"(p));
    return a;
}
__device__ __forceinline__ uint32_t swz(uint32_t b) { return b ^ ((b >> 3) & 0x70); }

__device__ __forceinline__ void ldsm4(uint32_t* r, uint32_t addr) {
    asm volatile("ldmatrix.sync.aligned.m8n8.x4.shared.b16 {%0,%1,%2,%3}, [%4];"
        : "=r"(r[0]), "=r"(r[1]), "=r"(r[2]), "=r"(r[3]) : "r"(addr));
}
__device__ __forceinline__ void mma16816(float* d, const uint32_t* a, const uint32_t* b) {
    asm volatile("mma.sync.aligned.m16n8k16.row.col.f32.bf16.bf16.f32 "
        "{%0,%1,%2,%3}, {%4,%5,%6,%7}, {%8,%9}, {%0,%1,%2,%3};"
        : "+f"(d[0]), "+f"(d[1]), "+f"(d[2]), "+f"(d[3])
        : "r"(a[0]), "r"(a[1]), "r"(a[2]), "r"(a[3]), "r"(b[0]), "r"(b[1]));
}
#define CP16(dst, src) asm volatile("cp.async.cg.shared.global [%0], [%1], 16;" :: "r"(dst), "l"(src))
#define CP_COMMIT()    asm volatile("cp.async.commit_group;" ::: "memory")
#define CP_WAIT0()     asm volatile("cp.async.wait_group 0;" ::: "memory")

// ---------------------------------------------------------------------------
// SMEM layout (dynamic): two 96KB stages + double-slotted sampling arrays
//   stage: P_hi 16K | P_lo 16K | W_hi 32K | W_lo 32K
// ---------------------------------------------------------------------------
#define STAGE_BYTES 98304
#define OFF_P_HI    0
#define OFF_P_LO    16384
#define OFF_W_HI    32768
#define OFF_W_LO    65536
#define OFF_SAMP_W  196608          // float[2][128][4]
#define OFF_SAMP_I  200704          // int[2][128][4]
#define SMEM_TOTAL  204800

// ---------------------------------------------------------------------------
// Kernel 0: weight prep — dw [o][c][k] fp32 -> [k][o][c] bf16 hi/lo
// ---------------------------------------------------------------------------
__global__ void __launch_bounds__(256) wt_prep_kernel(const float* __restrict__ dw) {
    int e = blockIdx.x * 256 + threadIdx.x;
    int c = e & 255;
    int o = (e >> 8) & 255;
    int k = e >> 16;
    float v = dw[((size_t)o * C_ + c) * K_ + k];
    __nv_bfloat16 h = __float2bfloat16(v);
    g_wtb_hi[e] = h;
    g_wtb_lo[e] = __float2bfloat16(v - __bfloat162float(h));
}

// ---------------------------------------------------------------------------
// Kernel 1: offset conv (3x3, pad 1, 256 -> 18 channels)
// ---------------------------------------------------------------------------
__global__ void __launch_bounds__(256) offset_conv_kernel(const float* __restrict__ x,
                                                          const float* __restrict__ ow) {
    __shared__ float w_s[64 * 180];
    int tid = threadIdx.x;
    int gid = blockIdx.x * 256 + tid;
    int b   = gid >> 12;
    int rem = gid & 4095;
    int ho  = rem >> 6, wo = rem & 63;

    float acc[20];
#pragma unroll
    for (int i = 0; i < 20; i++) acc[i] = 0.f;

    int xoff[9];
#pragma unroll
    for (int kh = 0; kh < 3; kh++)
#pragma unroll
        for (int kw = 0; kw < 3; kw++) {
            int y = ho - 1 + kh, xx = wo - 1 + kw;
            bool v = ((unsigned)y < 64u) && ((unsigned)xx < 64u);
            xoff[kh * 3 + kw] = v ? (y * 64 + xx) : -1;
        }

    const float* xb = x + (size_t)b * C_ * HW_;

    for (int c0 = 0; c0 < C_; c0 += 64) {
        __syncthreads();
        for (int i = tid; i < 64 * 180; i += 256) {
            int cc = i / 180, r = i % 180, tap = r / 20, ch = r % 20;
            w_s[i] = (ch < 18) ? ow[((size_t)ch * C_ + (c0 + cc)) * K_ + tap] : 0.f;
        }
        __syncthreads();

        for (int cc = 0; cc < 64; cc++) {
            const float* xp = xb + (size_t)(c0 + cc) * HW_;
            float xv[9];
#pragma unroll
            for (int t = 0; t < 9; t++) xv[t] = (xoff[t] >= 0) ? xp[xoff[t]] : 0.f;

            const float* wb = &w_s[cc * 180];
#pragma unroll
            for (int t = 0; t < 9; t++) {
                float v = xv[t];
#pragma unroll
                for (int q = 0; q < 5; q++) {
                    float4 w4 = *(const float4*)(wb + t * 20 + q * 4);
                    acc[q * 4 + 0] = fmaf(v, w4.x, acc[q * 4 + 0]);
                    acc[q * 4 + 1] = fmaf(v, w4.y, acc[q * 4 + 1]);
                    acc[q * 4 + 2] = fmaf(v, w4.z, acc[q * 4 + 2]);
                    acc[q * 4 + 3] = fmaf(v, w4.w, acc[q * 4 + 3]);
                }
            }
        }
    }
#pragma unroll
    for (int ch = 0; ch < 18; ch++)
        g_offset[((size_t)b * OCF_ + ch) * HW_ + rem] = acc[ch];
}

// ---------------------------------------------------------------------------
// Deform kernel device pieces
// ---------------------------------------------------------------------------
__device__ __forceinline__ void compute_samp(float* samp_w, int* samp_i,
                                             const float* g_off_b, int ho0,
                                             int k, int slot, int tid) {
    if (tid < 128) {
        int p = tid;
        int ho = ho0 + (p >> 6), wo2 = p & 63;
        const float* offp = g_off_b + ho * 64 + wo2;
        float dy = offp[(size_t)(2 * k) * HW_];
        float dx = offp[(size_t)(2 * k + 1) * HW_];
        float sy = (float)(ho - 1 + k / 3) + dy;
        float sx = (float)(wo2 - 1 + k % 3) + dx;
        float y0f = floorf(sy), x0f = floorf(sx);
        float ly = sy - y0f, lx = sx - x0f;
        int y0 = (int)y0f, x0 = (int)x0f;
        int base = slot * 512 + p * 4;
#pragma unroll
        for (int j = 0; j < 4; j++) {
            int yc = y0 + (j >> 1), xc = x0 + (j & 1);
            float wy = (j >> 1) ? ly : 1.f - ly;
            float wx = (j & 1)  ? lx : 1.f - lx;
            bool v = ((unsigned)yc < 64u) && ((unsigned)xc < 64u);
            samp_w[base + j] = v ? wy * wx : 0.f;
            samp_i[base + j] = min(max(yc, 0), 63) * 64 + min(max(xc, 0), 63);
        }
    }
}

// issue cp.async for weight stage of chunk (k, c0) into stage buffer
__device__ __forceinline__ void stage_weights_async(char* smem, int stage, int k, int c0, int tid) {
    const char* wh = (const char*)(g_wtb_hi + (size_t)k * CO_ * C_ + c0);
    const char* wl = (const char*)(g_wtb_lo + (size_t)k * CO_ * C_ + c0);
    uint32_t sbase = smem_u32(smem) + (uint32_t)stage * STAGE_BYTES;
#pragma unroll
    for (int i = 0; i < 8; i++) {
        int e = tid + i * 256;              // 0..2047
        int o = e >> 3, q = e & 7;
        uint32_t sw = swz((uint32_t)(o * 128 + q * 16));
        CP16(sbase + OFF_W_HI + sw, wh + (size_t)o * 512 + q * 16);
        CP16(sbase + OFF_W_LO + sw, wl + (size_t)o * 512 + q * 16);
    }
}

// ---------------------------------------------------------------------------
// Kernel 2: deformable conv via warp mma.sync, double-buffered pipeline.
// CTA = (b, row-pair): D[256 o][128 p], K = 9 taps x 4 c-chunks of 64.
// 8 warps = 4(o) x 2(p), warp tile 64x64.
// ---------------------------------------------------------------------------
__global__ void __launch_bounds__(256, 1) deform_mma_kernel(const float* __restrict__ x) {
    extern __shared__ char smem[];
    uint32_t sb = smem_u32(smem);
    int tid = threadIdx.x, wid = tid >> 5, lane = tid & 31;
    int blk = blockIdx.x;                 // 0..255
    int b   = blk >> 5;
    int rp  = blk & 31;
    int ho0 = rp * 2;
    int pos0 = ho0 * 64;
    int wo = wid >> 1;                    // o quarter
    int wp = wid & 1;                     // p half

    float* samp_w = (float*)(smem + OFF_SAMP_W);
    int*   samp_i = (int*)(smem + OFF_SAMP_I);
    const float* xb = x + (size_t)b * C_ * HW_;
    const float* goffb = g_offset + (size_t)b * OCF_ * HW_;

    float acc[4][8][4];
#pragma unroll
    for (int i = 0; i < 4; i++)
#pragma unroll
        for (int j = 0; j < 8; j++)
#pragma unroll
            for (int q = 0; q < 4; q++) acc[i][j][q] = 0.f;

    int mat = lane >> 3, mr = lane & 7;

    // ---------------- prologue: samp(tap0), stage 0 (W async + P gather) ----
    compute_samp(samp_w, samp_i, goffb, ho0, 0, 0, tid);
    stage_weights_async(smem, 0, 0, 0, tid);
    CP_COMMIT();
    __syncthreads();     // samp slot0 visible for gather
    {
#pragma unroll
        for (int g = 0; g < 4; g++) {
            int e  = g * 256 + tid;
            int p  = e & 127;
            int c8 = e >> 7;
            const float4 wv = *(const float4*)(samp_w + p * 4);
            const int4   iv = *(const int4*)(samp_i + p * 4);
            uint32_t hp[4], lp[4];
#pragma unroll
            for (int j = 0; j < 4; j++) {
                const float* xp0 = xb + (size_t)(c8 * 8 + j * 2) * HW_;
                const float* xp1 = xp0 + HW_;
                float v0 = wv.x * xp0[iv.x] + wv.y * xp0[iv.y]
                         + wv.z * xp0[iv.z] + wv.w * xp0[iv.w];
                float v1 = wv.x * xp1[iv.x] + wv.y * xp1[iv.y]
                         + wv.z * xp1[iv.z] + wv.w * xp1[iv.w];
                __nv_bfloat16 h0 = __float2bfloat16(v0);
                __nv_bfloat16 h1 = __float2bfloat16(v1);
                __nv_bfloat16 l0 = __float2bfloat16(v0 - __bfloat162float(h0));
                __nv_bfloat16 l1 = __float2bfloat16(v1 - __bfloat162float(h1));
                __nv_bfloat162 h2; h2.x = h0; h2.y = h1;
                __nv_bfloat162 l2; l2.x = l0; l2.y = l1;
                hp[j] = *(uint32_t*)&h2;
                lp[j] = *(uint32_t*)&l2;
            }
            uint32_t sw = swz((uint32_t)(p * 128 + c8 * 16));
            *(uint4*)(smem + OFF_P_HI + sw) = *(uint4*)hp;
            *(uint4*)(smem + OFF_P_LO + sw) = *(uint4*)lp;
        }
    }
    CP_WAIT0();
    __syncthreads();     // stage 0 ready

    // ---------------- main loop --------------------------------------------
#pragma unroll 1
    for (int chunk = 0; chunk < 36; chunk++) {
        int s = chunk & 1, n = s ^ 1;
        int kc = chunk >> 2;
        uint32_t cur = sb + (uint32_t)s * STAGE_BYTES;
        char* nxtp = smem + (size_t)n * STAGE_BYTES;

        bool produce = (chunk < 35);
        int kn = (chunk + 1) >> 2;
        int c0n = ((chunk + 1) & 3) << 6;
        int slotn = kn & 1;

        // samp for next tap (one tap ahead), off critical path
        if ((chunk & 3) == 0 && kc < 8)
            compute_samp(samp_w, samp_i, goffb, ho0, kc + 1, (kc + 1) & 1, tid);

        // async weight prefetch for chunk+1
        if (produce) {
            stage_weights_async(smem, n, kn, c0n, tid);
            CP_COMMIT();
        }

        // 4 k-steps: issue gather LDGs early, mma, then combine+STS
#pragma unroll
        for (int ks = 0; ks < 4; ks++) {
            // --- gather loads for chunk+1 (1 item/thread/ks) ---
            float cr0[4][4], cr1[4][4];
            float4 wv; int4 iv;
            int p_g = 0, c8_g = 0;
            if (produce) {
                int e  = ks * 256 + tid;
                p_g  = e & 127;
                c8_g = e >> 7;
                wv = *(const float4*)(samp_w + slotn * 512 + p_g * 4);
                iv = *(const int4*)(samp_i + slotn * 512 + p_g * 4);
#pragma unroll
                for (int j = 0; j < 4; j++) {
                    const float* xp0 = xb + (size_t)(c0n + c8_g * 8 + j * 2) * HW_;
                    const float* xp1 = xp0 + HW_;
                    cr0[j][0] = xp0[iv.x]; cr0[j][1] = xp0[iv.y];
                    cr0[j][2] = xp0[iv.z]; cr0[j][3] = xp0[iv.w];
                    cr1[j][0] = xp1[iv.x]; cr1[j][1] = xp1[iv.y];
                    cr1[j][2] = xp1[iv.z]; cr1[j][3] = xp1[iv.w];
                }
            }

            // --- A fragments (held across splits) ---
            uint32_t ah[4][4], al[4][4];
#pragma unroll
            for (int mt = 0; mt < 4; mt++) {
                uint32_t byte = (uint32_t)((wo * 64 + mt * 16 + (mat & 1) * 8 + mr) * 128
                                           + ks * 32 + (mat >> 1) * 16);
                uint32_t adr = swz(byte);
                ldsm4(ah[mt], cur + OFF_W_HI + adr);
                ldsm4(al[mt], cur + OFF_W_LO + adr);
            }

            // --- 3 splits, each 32 mmas over distinct accumulators ---
#pragma unroll
            for (int sp = 0; sp < 3; sp++) {
                uint32_t poff = (sp == 1) ? (uint32_t)OFF_P_LO : (uint32_t)OFF_P_HI;
#pragma unroll
                for (int np = 0; np < 4; np++) {
                    uint32_t byte = (uint32_t)((wp * 64 + np * 16 + (mat >> 1) * 8 + mr) * 128
                                               + ks * 32 + (mat & 1) * 16);
                    uint32_t adr = swz(byte);
                    uint32_t bfr[4];
                    ldsm4(bfr, cur + poff + adr);
#pragma unroll
                    for (int mt = 0; mt < 4; mt++) {
                        const uint32_t* afr = (sp == 2) ? al[mt] : ah[mt];
                        mma16816(acc[mt][2 * np],     afr, bfr);
                        mma16816(acc[mt][2 * np + 1], afr, bfr + 2);
                    }
                }
            }

            // --- combine + STS into next stage P ---
            if (produce) {
                uint32_t hp[4], lp[4];
#pragma unroll
                for (int j = 0; j < 4; j++) {
                    float v0 = wv.x * cr0[j][0] + wv.y * cr0[j][1]
                             + wv.z * cr0[j][2] + wv.w * cr0[j][3];
                    float v1 = wv.x * cr1[j][0] + wv.y * cr1[j][1]
                             + wv.z * cr1[j][2] + wv.w * cr1[j][3];
                    __nv_bfloat16 h0 = __float2bfloat16(v0);
                    __nv_bfloat16 h1 = __float2bfloat16(v1);
                    __nv_bfloat16 l0 = __float2bfloat16(v0 - __bfloat162float(h0));
                    __nv_bfloat16 l1 = __float2bfloat16(v1 - __bfloat162float(h1));
                    __nv_bfloat162 h2; h2.x = h0; h2.y = h1;
                    __nv_bfloat162 l2; l2.x = l0; l2.y = l1;
                    hp[j] = *(uint32_t*)&h2;
                    lp[j] = *(uint32_t*)&l2;
                }
                uint32_t sw = swz((uint32_t)(p_g * 128 + c8_g * 16));
                *(uint4*)(nxtp + OFF_P_HI + sw) = *(uint4*)hp;
                *(uint4*)(nxtp + OFF_P_LO + sw) = *(uint4*)lp;
            }
        }

        CP_WAIT0();
        __syncthreads();   // next stage fully staged; cur stage free
    }

    // ---------------- epilogue ----------------------------------------------
    int l4 = lane >> 2, l2 = (lane & 3) * 2;
#pragma unroll
    for (int mt = 0; mt < 4; mt++) {
#pragma unroll
        for (int nt = 0; nt < 8; nt++) {
            int o = wo * 64 + mt * 16 + l4;
            int p = wp * 64 + nt * 8 + l2;
            float* dst = g_y + ((size_t)(b * CO_ + o)) * HW_ + pos0 + p;
            *(float2*)dst = make_float2(acc[mt][nt][0], acc[mt][nt][1]);
            *(float2*)(dst + (size_t)8 * HW_) = make_float2(acc[mt][nt][2], acc[mt][nt][3]);
        }
    }
}

// ---------------------------------------------------------------------------
// Kernel 3: channel attention
// ---------------------------------------------------------------------------
__global__ void __launch_bounds__(256) attn_kernel(float* __restrict__ out) {
    int bo = blockIdx.x;
    const float4* yp = (const float4*)(g_y + (size_t)bo * HW_);
    int tid = threadIdx.x;

    float s = 0.f, s2 = 0.f;
    float4 v[4];
#pragma unroll
    for (int i = 0; i < 4; i++) {
        v[i] = yp[tid + i * 256];
        s  += v[i].x + v[i].y + v[i].z + v[i].w;
        s2 += v[i].x * v[i].x + v[i].y * v[i].y + v[i].z * v[i].z + v[i].w * v[i].w;
    }
#pragma unroll
    for (int off = 16; off; off >>= 1) {
        s  += __shfl_down_sync(0xffffffffu, s,  off);
        s2 += __shfl_down_sync(0xffffffffu, s2, off);
    }
    __shared__ float rs[8], rs2[8];
    __shared__ float sa;
    int lane = tid & 31, w = tid >> 5;
    if (lane == 0) { rs[w] = s; rs2[w] = s2; }
    __syncthreads();
    if (tid == 0) {
        float S = 0.f, S2 = 0.f;
#pragma unroll
        for (int i = 0; i < 8; i++) { S += rs[i]; S2 += rs2[i]; }
        float mean = S * (1.f / 4096.f);
        float var  = (S2 - S * S * (1.f / 4096.f)) * (1.f / 4095.f);
        float sd   = sqrtf(fmaxf(var, 0.f));
        sa = 1.f / (1.f + expf(-(mean + sd)));
    }
    __syncthreads();
    float a = sa;
    float4* op = (float4*)(out + (size_t)bo * HW_);
#pragma unroll
    for (int i = 0; i < 4; i++) {
        float4 u = v[i];
        u.x *= a; u.y *= a; u.z *= a; u.w *= a;
        op[tid + i * 256] = u;
    }
}

// ---------------------------------------------------------------------------
extern "C" void kernel_launch(void* const* d_in, const int* in_sizes, int n_in,
                              void* d_out, int out_size) {
    const float* x  = (const float*)d_in[0];   // [8,256,64,64]
    const float* ow = (const float*)d_in[1];   // [18,256,3,3]
    const float* dw = (const float*)d_in[2];   // [256,256,3,3]
    float* out = (float*)d_out;                // [8,256,64,64]

    cudaFuncSetAttribute(deform_mma_kernel,
                         cudaFuncAttributeMaxDynamicSharedMemorySize, SMEM_TOTAL);

    wt_prep_kernel<<<(K_ * CO_ * C_) / 256, 256>>>(dw);
    offset_conv_kernel<<<(B_ * HW_) / 256, 256>>>(x, ow);
    deform_mma_kernel<<<B_ * 32, 256, SMEM_TOTAL>>>(x);
    attn_kernel<<<B_ * CO_, 256>>>(out);
}

// round 6
// speedup vs baseline: 2.9141x; 1.1083x over previous
#include <cuda_runtime.h>
#include <cuda_bf16.h>
#include <math.h>
#include <stdint.h>

// Problem constants
#define B_   8
#define C_   256
#define H_   64
#define W_   64
#define HW_  4096
#define CO_  256
#define OCF_ 18
#define K_   9

// ---------------------------------------------------------------------------
// Device-global scratch
// ---------------------------------------------------------------------------
__device__ float g_offset[B_ * OCF_ * HW_];        // [B,18,H,W]
__device__ float g_wt[K_ * CO_ * C_];              // [k][o][c] fp32 (tf32-rounded)
__device__ float g_y[B_ * CO_ * HW_];              // pre-attention output

// ---------------------------------------------------------------------------
// Helpers (baseline PTX: ldmatrix / mma.sync tf32 / cp.async — all sm_80+)
// ---------------------------------------------------------------------------
__device__ __forceinline__ uint32_t smem_u32(const void* p) {
    uint32_t a;
    asm("{ .reg .u64 t; cvta.to.shared.u64 t, %1; cvt.u32.u64 %0, t; }" : "=r"(a) : "l"(p));
    return a;
}
__device__ __forceinline__ uint32_t swz(uint32_t b) { return b ^ ((b >> 3) & 0x70); }

__device__ __forceinline__ void ldsm4(uint32_t* r, uint32_t addr) {
    asm volatile("ldmatrix.sync.aligned.m8n8.x4.shared.b16 {%0,%1,%2,%3}, [%4];"
        : "=r"(r[0]), "=r"(r[1]), "=r"(r[2]), "=r"(r[3]) : "r"(addr));
}
__device__ __forceinline__ void mma_tf32(float* d, const uint32_t* a, const uint32_t* b) {
    asm volatile("mma.sync.aligned.m16n8k8.row.col.f32.tf32.tf32.f32 "
        "{%0,%1,%2,%3}, {%4,%5,%6,%7}, {%8,%9}, {%0,%1,%2,%3};"
        : "+f"(d[0]), "+f"(d[1]), "+f"(d[2]), "+f"(d[3])
        : "r"(a[0]), "r"(a[1]), "r"(a[2]), "r"(a[3]), "r"(b[0]), "r"(b[1]));
}
__device__ __forceinline__ uint32_t f2tf32(float v) {
    uint32_t r;
    asm("cvt.rna.tf32.f32 %0, %1;" : "=r"(r) : "f"(v));
    return r;
}
#define CP16(dst, src) asm volatile("cp.async.cg.shared.global [%0], [%1], 16;" :: "r"(dst), "l"(src))
#define CP_COMMIT()    asm volatile("cp.async.commit_group;" ::: "memory")
#define CP_WAIT0()     asm volatile("cp.async.wait_group 0;" ::: "memory")

// ---------------------------------------------------------------------------
// SMEM layout: two 48KB stages (P [128p][32c] fp32 16K | W [256o][32c] fp32 32K)
// ---------------------------------------------------------------------------
#define STAGE_BYTES 49152
#define OFF_P       0
#define OFF_W       16384
#define OFF_SAMP_W  98304           // float[2][128][4]
#define OFF_SAMP_I  102400          // int[2][128][4]
#define SMEM_TOTAL  106496

// ---------------------------------------------------------------------------
// Kernel 0: weight prep — dw [o][c][k] fp32 -> g_wt [k][o][c], tf32-rounded
// ---------------------------------------------------------------------------
__global__ void __launch_bounds__(256) wt_prep_kernel(const float* __restrict__ dw) {
    int e = blockIdx.x * 256 + threadIdx.x;
    int c = e & 255;
    int o = (e >> 8) & 255;
    int k = e >> 16;
    float v = dw[((size_t)o * C_ + c) * K_ + k];
    uint32_t t = f2tf32(v);
    ((uint32_t*)g_wt)[e] = t;
}

// ---------------------------------------------------------------------------
// Kernel 1: offset conv (3x3, pad 1, 256 -> 18 channels) — fp32 exact
// ---------------------------------------------------------------------------
__global__ void __launch_bounds__(256) offset_conv_kernel(const float* __restrict__ x,
                                                          const float* __restrict__ ow) {
    __shared__ float w_s[64 * 180];
    int tid = threadIdx.x;
    int gid = blockIdx.x * 256 + tid;
    int b   = gid >> 12;
    int rem = gid & 4095;
    int ho  = rem >> 6, wo = rem & 63;

    float acc[20];
#pragma unroll
    for (int i = 0; i < 20; i++) acc[i] = 0.f;

    int xoff[9];
#pragma unroll
    for (int kh = 0; kh < 3; kh++)
#pragma unroll
        for (int kw = 0; kw < 3; kw++) {
            int y = ho - 1 + kh, xx = wo - 1 + kw;
            bool v = ((unsigned)y < 64u) && ((unsigned)xx < 64u);
            xoff[kh * 3 + kw] = v ? (y * 64 + xx) : -1;
        }

    const float* xb = x + (size_t)b * C_ * HW_;

    for (int c0 = 0; c0 < C_; c0 += 64) {
        __syncthreads();
        for (int i = tid; i < 64 * 180; i += 256) {
            int cc = i / 180, r = i % 180, tap = r / 20, ch = r % 20;
            w_s[i] = (ch < 18) ? ow[((size_t)ch * C_ + (c0 + cc)) * K_ + tap] : 0.f;
        }
        __syncthreads();

        for (int cc = 0; cc < 64; cc++) {
            const float* xp = xb + (size_t)(c0 + cc) * HW_;
            float xv[9];
#pragma unroll
            for (int t = 0; t < 9; t++) xv[t] = (xoff[t] >= 0) ? xp[xoff[t]] : 0.f;

            const float* wb = &w_s[cc * 180];
#pragma unroll
            for (int t = 0; t < 9; t++) {
                float v = xv[t];
#pragma unroll
                for (int q = 0; q < 5; q++) {
                    float4 w4 = *(const float4*)(wb + t * 20 + q * 4);
                    acc[q * 4 + 0] = fmaf(v, w4.x, acc[q * 4 + 0]);
                    acc[q * 4 + 1] = fmaf(v, w4.y, acc[q * 4 + 1]);
                    acc[q * 4 + 2] = fmaf(v, w4.z, acc[q * 4 + 2]);
                    acc[q * 4 + 3] = fmaf(v, w4.w, acc[q * 4 + 3]);
                }
            }
        }
    }
#pragma unroll
    for (int ch = 0; ch < 18; ch++)
        g_offset[((size_t)b * OCF_ + ch) * HW_ + rem] = acc[ch];
}

// ---------------------------------------------------------------------------
// Deform kernel device pieces
// ---------------------------------------------------------------------------
__device__ __forceinline__ void compute_samp(float* samp_w, int* samp_i,
                                             const float* g_off_b, int ho0,
                                             int k, int slot, int tid) {
    if (tid < 128) {
        int p = tid;
        int ho = ho0 + (p >> 6), wo2 = p & 63;
        const float* offp = g_off_b + ho * 64 + wo2;
        float dy = offp[(size_t)(2 * k) * HW_];
        float dx = offp[(size_t)(2 * k + 1) * HW_];
        float sy = (float)(ho - 1 + k / 3) + dy;
        float sx = (float)(wo2 - 1 + k % 3) + dx;
        float y0f = floorf(sy), x0f = floorf(sx);
        float ly = sy - y0f, lx = sx - x0f;
        int y0 = (int)y0f, x0 = (int)x0f;
        int base = slot * 512 + p * 4;
#pragma unroll
        for (int j = 0; j < 4; j++) {
            int yc = y0 + (j >> 1), xc = x0 + (j & 1);
            float wy = (j >> 1) ? ly : 1.f - ly;
            float wx = (j & 1)  ? lx : 1.f - lx;
            bool v = ((unsigned)yc < 64u) && ((unsigned)xc < 64u);
            samp_w[base + j] = v ? wy * wx : 0.f;
            samp_i[base + j] = min(max(yc, 0), 63) * 64 + min(max(xc, 0), 63);
        }
    }
}

// async weight stage: g_wt[k][o][c0..c0+31] fp32 -> stage W [256o][32c] swizzled
__device__ __forceinline__ void stage_weights_async(uint32_t sbase, int k, int c0, int tid) {
    const char* wsrc = (const char*)g_wt + ((size_t)k * CO_ * C_ + c0) * 4;
#pragma unroll
    for (int i = 0; i < 8; i++) {
        int e = tid + i * 256;              // 0..2047
        int o = e >> 3, q = e & 7;
        uint32_t sw = swz((uint32_t)(o * 128 + q * 16));
        CP16(sbase + OFF_W + sw, wsrc + (size_t)o * 1024 + q * 16);
    }
}

// ---------------------------------------------------------------------------
// Kernel 2: deformable conv via tf32 mma.sync, double-buffered pipeline.
// CTA = (b, row-pair): D[256 o][128 p], K = 9 taps x 8 c-chunks of 32.
// 8 warps = 4(o) x 2(p), warp tile 64x64.
// ---------------------------------------------------------------------------
__global__ void __launch_bounds__(256, 1) deform_mma_kernel(const float* __restrict__ x) {
    extern __shared__ char smem[];
    uint32_t sb = smem_u32(smem);
    int tid = threadIdx.x, wid = tid >> 5, lane = tid & 31;
    int blk = blockIdx.x;                 // 0..255
    int b   = blk >> 5;
    int rp  = blk & 31;
    int ho0 = rp * 2;
    int pos0 = ho0 * 64;
    int wo = wid >> 1;                    // o quarter
    int wp = wid & 1;                     // p half

    float* samp_w = (float*)(smem + OFF_SAMP_W);
    int*   samp_i = (int*)(smem + OFF_SAMP_I);
    const float* xb = x + (size_t)b * C_ * HW_;
    const float* goffb = g_offset + (size_t)b * OCF_ * HW_;

    float acc[4][8][4];
#pragma unroll
    for (int i = 0; i < 4; i++)
#pragma unroll
        for (int j = 0; j < 8; j++)
#pragma unroll
            for (int q = 0; q < 4; q++) acc[i][j][q] = 0.f;

    int mat = lane >> 3, mr = lane & 7;

    // ---------------- prologue: samp(tap0), stage 0 (W async + P gather) ----
    compute_samp(samp_w, samp_i, goffb, ho0, 0, 0, tid);
    stage_weights_async(sb, 0, 0, tid);
    CP_COMMIT();
    __syncthreads();     // samp slot0 visible
    {
#pragma unroll
        for (int g = 0; g < 4; g++) {
            int e  = g * 256 + tid;         // 0..1023
            int p  = e & 127;
            int c4 = e >> 7;                // group of 4 channels
            const float4 wv = *(const float4*)(samp_w + p * 4);
            const int4   iv = *(const int4*)(samp_i + p * 4);
            uint32_t tv[4];
#pragma unroll
            for (int j = 0; j < 4; j++) {
                const float* xp = xb + (size_t)(c4 * 4 + j) * HW_;
                float v = wv.x * xp[iv.x] + wv.y * xp[iv.y]
                        + wv.z * xp[iv.z] + wv.w * xp[iv.w];
                tv[j] = f2tf32(v);
            }
            uint32_t sw = swz((uint32_t)(p * 128 + c4 * 16));
            *(uint4*)(smem + OFF_P + sw) = *(uint4*)tv;
        }
    }
    CP_WAIT0();
    __syncthreads();     // stage 0 ready

    // ---------------- main loop: 72 chunks of c=32 ---------------------------
#pragma unroll 1
    for (int chunk = 0; chunk < 72; chunk++) {
        int s = chunk & 1, n = s ^ 1;
        int kc = chunk >> 3;
        uint32_t cur = sb + (uint32_t)s * STAGE_BYTES;
        uint32_t nxt = sb + (uint32_t)n * STAGE_BYTES;
        char* nxtp = smem + (size_t)n * STAGE_BYTES;

        bool produce = (chunk < 71);
        int kn = (chunk + 1) >> 3;
        int c0n = ((chunk + 1) & 7) << 5;
        int slotn = kn & 1;

        // samp for next tap (one tap ahead), off critical path
        if ((chunk & 7) == 0 && kc < 8)
            compute_samp(samp_w, samp_i, goffb, ho0, kc + 1, (kc + 1) & 1, tid);

        // async weight prefetch for chunk+1
        if (produce) {
            stage_weights_async(nxt, kn, c0n, tid);
            CP_COMMIT();
        }

        // 4 k8-steps: gather LDGs early, mma, combine+STS
#pragma unroll
        for (int ks = 0; ks < 4; ks++) {
            // --- gather loads for chunk+1 (1 quad-item/thread/ks) ---
            float cr[4][4];
            float4 wv; int4 iv;
            int p_g = 0, c4_g = 0;
            if (produce) {
                int e  = ks * 256 + tid;
                p_g  = e & 127;
                c4_g = e >> 7;
                wv = *(const float4*)(samp_w + slotn * 512 + p_g * 4);
                iv = *(const int4*)(samp_i + slotn * 512 + p_g * 4);
#pragma unroll
                for (int j = 0; j < 4; j++) {
                    const float* xp = xb + (size_t)(c0n + c4_g * 4 + j) * HW_;
                    cr[j][0] = xp[iv.x]; cr[j][1] = xp[iv.y];
                    cr[j][2] = xp[iv.z]; cr[j][3] = xp[iv.w];
                }
            }

            // --- A fragments: 4 ldsm.x4 (o-tiles) ---
            uint32_t af[4][4];
#pragma unroll
            for (int mt = 0; mt < 4; mt++) {
                uint32_t byte = (uint32_t)((wo * 64 + mt * 16 + (mat & 1) * 8 + mr) * 128
                                           + ks * 32 + (mat >> 1) * 16);
                ldsm4(af[mt], cur + OFF_W + swz(byte));
            }
            // --- B fragments: 4 ldsm.x4 (each covers 2 n-tiles) ---
            uint32_t bf[4][4];
#pragma unroll
            for (int nb = 0; nb < 4; nb++) {
                uint32_t byte = (uint32_t)((wp * 64 + nb * 16 + (mat >> 1) * 8 + mr) * 128
                                           + ks * 32 + (mat & 1) * 16);
                ldsm4(bf[nb], cur + OFF_P + swz(byte));
            }

            // --- 32 mmas, max accumulator reuse distance ---
#pragma unroll
            for (int nb = 0; nb < 4; nb++) {
#pragma unroll
                for (int half = 0; half < 2; half++) {
#pragma unroll
                    for (int mt = 0; mt < 4; mt++) {
                        mma_tf32(acc[mt][2 * nb + half], af[mt], bf[nb] + 2 * half);
                    }
                }
            }

            // --- combine + cvt + STS into next stage P ---
            if (produce) {
                uint32_t tv[4];
#pragma unroll
                for (int j = 0; j < 4; j++) {
                    float v = wv.x * cr[j][0] + wv.y * cr[j][1]
                            + wv.z * cr[j][2] + wv.w * cr[j][3];
                    tv[j] = f2tf32(v);
                }
                uint32_t sw = swz((uint32_t)(p_g * 128 + c4_g * 16));
                *(uint4*)(nxtp + OFF_P + sw) = *(uint4*)tv;
            }
        }

        CP_WAIT0();
        __syncthreads();   // next stage staged; cur stage free
    }

    // ---------------- epilogue ----------------------------------------------
    int l4 = lane >> 2, l2 = (lane & 3) * 2;
#pragma unroll
    for (int mt = 0; mt < 4; mt++) {
#pragma unroll
        for (int nt = 0; nt < 8; nt++) {
            int o = wo * 64 + mt * 16 + l4;
            int p = wp * 64 + nt * 8 + l2;
            float* dst = g_y + ((size_t)(b * CO_ + o)) * HW_ + pos0 + p;
            *(float2*)dst = make_float2(acc[mt][nt][0], acc[mt][nt][1]);
            *(float2*)(dst + (size_t)8 * HW_) = make_float2(acc[mt][nt][2], acc[mt][nt][3]);
        }
    }
}

// ---------------------------------------------------------------------------
// Kernel 3: channel attention
// ---------------------------------------------------------------------------
__global__ void __launch_bounds__(256) attn_kernel(float* __restrict__ out) {
    int bo = blockIdx.x;
    const float4* yp = (const float4*)(g_y + (size_t)bo * HW_);
    int tid = threadIdx.x;

    float s = 0.f, s2 = 0.f;
    float4 v[4];
#pragma unroll
    for (int i = 0; i < 4; i++) {
        v[i] = yp[tid + i * 256];
        s  += v[i].x + v[i].y + v[i].z + v[i].w;
        s2 += v[i].x * v[i].x + v[i].y * v[i].y + v[i].z * v[i].z + v[i].w * v[i].w;
    }
#pragma unroll
    for (int off = 16; off; off >>= 1) {
        s  += __shfl_down_sync(0xffffffffu, s,  off);
        s2 += __shfl_down_sync(0xffffffffu, s2, off);
    }
    __shared__ float rs[8], rs2[8];
    __shared__ float sa;
    int lane = tid & 31, w = tid >> 5;
    if (lane == 0) { rs[w] = s; rs2[w] = s2; }
    __syncthreads();
    if (tid == 0) {
        float S = 0.f, S2 = 0.f;
#pragma unroll
        for (int i = 0; i < 8; i++) { S += rs[i]; S2 += rs2[i]; }
        float mean = S * (1.f / 4096.f);
        float var  = (S2 - S * S * (1.f / 4096.f)) * (1.f / 4095.f);
        float sd   = sqrtf(fmaxf(var, 0.f));
        sa = 1.f / (1.f + expf(-(mean + sd)));
    }
    __syncthreads();
    float a = sa;
    float4* op = (float4*)(out + (size_t)bo * HW_);
#pragma unroll
    for (int i = 0; i < 4; i++) {
        float4 u = v[i];
        u.x *= a; u.y *= a; u.z *= a; u.w *= a;
        op[tid + i * 256] = u;
    }
}

// ---------------------------------------------------------------------------
extern "C" void kernel_launch(void* const* d_in, const int* in_sizes, int n_in,
                              void* d_out, int out_size) {
    const float* x  = (const float*)d_in[0];   // [8,256,64,64]
    const float* ow = (const float*)d_in[1];   // [18,256,3,3]
    const float* dw = (const float*)d_in[2];   // [256,256,3,3]
    float* out = (float*)d_out;                // [8,256,64,64]

    cudaFuncSetAttribute(deform_mma_kernel,
                         cudaFuncAttributeMaxDynamicSharedMemorySize, SMEM_TOTAL);

    wt_prep_kernel<<<(K_ * CO_ * C_) / 256, 256>>>(dw);
    offset_conv_kernel<<<(B_ * HW_) / 256, 256>>>(x, ow);
    deform_mma_kernel<<<B_ * 32, 256, SMEM_TOTAL>>>(x);
    attn_kernel<<<B_ * CO_, 256>>>(out);
}

// round 7
// speedup vs baseline: 3.5625x; 1.2225x over previous
#include <cuda_runtime.h>
#include <cuda_fp16.h>
#include <math.h>
#include <stdint.h>

// Problem constants
#define B_   8
#define C_   256
#define H_   64
#define W_   64
#define HW_  4096
#define CO_  256
#define OCF_ 18
#define K_   9

// ---------------------------------------------------------------------------
// Device-global scratch
// ---------------------------------------------------------------------------
__device__ float g_offset[B_ * OCF_ * HW_];        // [B,18,H,W]
__device__ __half g_wth[K_ * CO_ * C_];            // [k][o][c] fp16 weights
__device__ float g_y[B_ * CO_ * HW_];              // pre-attention output

// ---------------------------------------------------------------------------
// Helpers (baseline PTX: ldmatrix / mma.sync fp16 / cp.async — all sm_80+)
// ---------------------------------------------------------------------------
__device__ __forceinline__ uint32_t smem_u32(const void* p) {
    uint32_t a;
    asm("{ .reg .u64 t; cvta.to.shared.u64 t, %1; cvt.u32.u64 %0, t; }" : "=r"(a) : "l"(p));
    return a;
}
__device__ __forceinline__ uint32_t swz(uint32_t b) { return b ^ ((b >> 3) & 0x70); }

__device__ __forceinline__ void ldsm4(uint32_t* r, uint32_t addr) {
    asm volatile("ldmatrix.sync.aligned.m8n8.x4.shared.b16 {%0,%1,%2,%3}, [%4];"
        : "=r"(r[0]), "=r"(r[1]), "=r"(r[2]), "=r"(r[3]) : "r"(addr));
}
__device__ __forceinline__ void mma_f16(float* d, const uint32_t* a, const uint32_t* b) {
    asm volatile("mma.sync.aligned.m16n8k16.row.col.f32.f16.f16.f32 "
        "{%0,%1,%2,%3}, {%4,%5,%6,%7}, {%8,%9}, {%0,%1,%2,%3};"
        : "+f"(d[0]), "+f"(d[1]), "+f"(d[2]), "+f"(d[3])
        : "r"(a[0]), "r"(a[1]), "r"(a[2]), "r"(a[3]), "r"(b[0]), "r"(b[1]));
}
#define CP16(dst, src) asm volatile("cp.async.cg.shared.global [%0], [%1], 16;" :: "r"(dst), "l"(src))
#define CP_COMMIT()    asm volatile("cp.async.commit_group;" ::: "memory")
#define CP_WAIT0()     asm volatile("cp.async.wait_group 0;" ::: "memory")

// ---------------------------------------------------------------------------
// SMEM: two 48KB stages  (P [128p][64c] fp16 16K | W [256o][64c] fp16 32K)
// ---------------------------------------------------------------------------
#define STAGE_BYTES 49152
#define OFF_P       0
#define OFF_W       16384
#define OFF_SAMP_W  98304           // float[2][128][4]
#define OFF_SAMP_I  102400          // int[2][128][4]
#define SMEM_TOTAL  106496

// ---------------------------------------------------------------------------
// Kernel 0: weight prep — dw [o][c][k] fp32 -> g_wth [k][o][c] fp16
// ---------------------------------------------------------------------------
__global__ void __launch_bounds__(256) wt_prep_kernel(const float* __restrict__ dw) {
    int e = blockIdx.x * 256 + threadIdx.x;
    int c = e & 255;
    int o = (e >> 8) & 255;
    int k = e >> 16;
    g_wth[e] = __float2half(dw[((size_t)o * C_ + c) * K_ + k]);
}

// ---------------------------------------------------------------------------
// Kernel 1: offset conv (3x3, pad 1, 256 -> 18 channels) — fp32 exact
// ---------------------------------------------------------------------------
__global__ void __launch_bounds__(256) offset_conv_kernel(const float* __restrict__ x,
                                                          const float* __restrict__ ow) {
    __shared__ float w_s[64 * 180];
    int tid = threadIdx.x;
    int gid = blockIdx.x * 256 + tid;
    int b   = gid >> 12;
    int rem = gid & 4095;
    int ho  = rem >> 6, wo = rem & 63;

    float acc[20];
#pragma unroll
    for (int i = 0; i < 20; i++) acc[i] = 0.f;

    int xoff[9];
#pragma unroll
    for (int kh = 0; kh < 3; kh++)
#pragma unroll
        for (int kw = 0; kw < 3; kw++) {
            int y = ho - 1 + kh, xx = wo - 1 + kw;
            bool v = ((unsigned)y < 64u) && ((unsigned)xx < 64u);
            xoff[kh * 3 + kw] = v ? (y * 64 + xx) : -1;
        }

    const float* xb = x + (size_t)b * C_ * HW_;

    for (int c0 = 0; c0 < C_; c0 += 64) {
        __syncthreads();
        for (int i = tid; i < 64 * 180; i += 256) {
            int cc = i / 180, r = i % 180, tap = r / 20, ch = r % 20;
            w_s[i] = (ch < 18) ? ow[((size_t)ch * C_ + (c0 + cc)) * K_ + tap] : 0.f;
        }
        __syncthreads();

        for (int cc = 0; cc < 64; cc++) {
            const float* xp = xb + (size_t)(c0 + cc) * HW_;
            float xv[9];
#pragma unroll
            for (int t = 0; t < 9; t++) xv[t] = (xoff[t] >= 0) ? xp[xoff[t]] : 0.f;

            const float* wb = &w_s[cc * 180];
#pragma unroll
            for (int t = 0; t < 9; t++) {
                float v = xv[t];
#pragma unroll
                for (int q = 0; q < 5; q++) {
                    float4 w4 = *(const float4*)(wb + t * 20 + q * 4);
                    acc[q * 4 + 0] = fmaf(v, w4.x, acc[q * 4 + 0]);
                    acc[q * 4 + 1] = fmaf(v, w4.y, acc[q * 4 + 1]);
                    acc[q * 4 + 2] = fmaf(v, w4.z, acc[q * 4 + 2]);
                    acc[q * 4 + 3] = fmaf(v, w4.w, acc[q * 4 + 3]);
                }
            }
        }
    }
#pragma unroll
    for (int ch = 0; ch < 18; ch++)
        g_offset[((size_t)b * OCF_ + ch) * HW_ + rem] = acc[ch];
}

// ---------------------------------------------------------------------------
// Deform kernel device pieces
// ---------------------------------------------------------------------------
__device__ __forceinline__ void compute_samp(float* samp_w, int* samp_i,
                                             const float* g_off_b, int ho0,
                                             int k, int slot, int tid) {
    if (tid < 128) {
        int p = tid;
        int ho = ho0 + (p >> 6), wo2 = p & 63;
        const float* offp = g_off_b + ho * 64 + wo2;
        float dy = offp[(size_t)(2 * k) * HW_];
        float dx = offp[(size_t)(2 * k + 1) * HW_];
        float sy = (float)(ho - 1 + k / 3) + dy;
        float sx = (float)(wo2 - 1 + k % 3) + dx;
        float y0f = floorf(sy), x0f = floorf(sx);
        float ly = sy - y0f, lx = sx - x0f;
        int y0 = (int)y0f, x0 = (int)x0f;
        int base = slot * 512 + p * 4;
#pragma unroll
        for (int j = 0; j < 4; j++) {
            int yc = y0 + (j >> 1), xc = x0 + (j & 1);
            float wy = (j >> 1) ? ly : 1.f - ly;
            float wx = (j & 1)  ? lx : 1.f - lx;
            bool v = ((unsigned)yc < 64u) && ((unsigned)xc < 64u);
            samp_w[base + j] = v ? wy * wx : 0.f;
            samp_i[base + j] = min(max(yc, 0), 63) * 64 + min(max(xc, 0), 63);
        }
    }
}

// async weight stage: g_wth[k][o][c0..c0+63] fp16 -> stage W [256o][64c] swizzled
__device__ __forceinline__ void stage_weights_async(uint32_t sbase, int k, int c0, int tid) {
    const char* wsrc = (const char*)g_wth + ((size_t)k * CO_ * C_ + c0) * 2;
#pragma unroll
    for (int i = 0; i < 8; i++) {
        int e = tid + i * 256;              // 0..2047
        int o = e >> 3, q = e & 7;
        uint32_t sw = swz((uint32_t)(o * 128 + q * 16));
        CP16(sbase + OFF_W + sw, wsrc + (size_t)o * 512 + q * 16);
    }
}

// ---------------------------------------------------------------------------
// Kernel 2: deformable conv via fp16 mma.sync (single pass), double-buffered.
// CTA = (b, row-pair): D[256 o][128 p], K = 9 taps x 4 c-chunks of 64.
// 8 warps = 4(o) x 2(p), warp tile 64x64.
// ---------------------------------------------------------------------------
__global__ void __launch_bounds__(256, 1) deform_mma_kernel(const float* __restrict__ x) {
    extern __shared__ char smem[];
    uint32_t sb = smem_u32(smem);
    int tid = threadIdx.x, wid = tid >> 5, lane = tid & 31;
    int blk = blockIdx.x;                 // 0..255
    int b   = blk >> 5;
    int rp  = blk & 31;
    int ho0 = rp * 2;
    int pos0 = ho0 * 64;
    int wo = wid >> 1;                    // o quarter
    int wp = wid & 1;                     // p half

    float* samp_w = (float*)(smem + OFF_SAMP_W);
    int*   samp_i = (int*)(smem + OFF_SAMP_I);
    const float* xb = x + (size_t)b * C_ * HW_;
    const float* goffb = g_offset + (size_t)b * OCF_ * HW_;

    float acc[4][8][4];
#pragma unroll
    for (int i = 0; i < 4; i++)
#pragma unroll
        for (int j = 0; j < 8; j++)
#pragma unroll
            for (int q = 0; q < 4; q++) acc[i][j][q] = 0.f;

    int mat = lane >> 3, mr = lane & 7;

    // ---------------- prologue: samp(tap0), stage 0 (W async + P gather) ----
    compute_samp(samp_w, samp_i, goffb, ho0, 0, 0, tid);
    stage_weights_async(sb, 0, 0, tid);
    CP_COMMIT();
    __syncthreads();     // samp slot0 visible
    {
#pragma unroll
        for (int g = 0; g < 4; g++) {
            int e  = g * 256 + tid;         // 0..1023
            int p  = e & 127;
            int c8 = e >> 7;                // group of 8 channels
            const float4 wv = *(const float4*)(samp_w + p * 4);
            const int4   iv = *(const int4*)(samp_i + p * 4);
            uint32_t hp[4];
#pragma unroll
            for (int j = 0; j < 4; j++) {
                const float* xp0 = xb + (size_t)(c8 * 8 + j * 2) * HW_;
                const float* xp1 = xp0 + HW_;
                float v0 = wv.x * xp0[iv.x] + wv.y * xp0[iv.y]
                         + wv.z * xp0[iv.z] + wv.w * xp0[iv.w];
                float v1 = wv.x * xp1[iv.x] + wv.y * xp1[iv.y]
                         + wv.z * xp1[iv.z] + wv.w * xp1[iv.w];
                __half2 h2 = __floats2half2_rn(v0, v1);
                hp[j] = *(uint32_t*)&h2;
            }
            uint32_t sw = swz((uint32_t)(p * 128 + c8 * 16));
            *(uint4*)(smem + OFF_P + sw) = *(uint4*)hp;
        }
    }
    CP_WAIT0();
    __syncthreads();     // stage 0 ready

    // ---------------- main loop: 36 chunks of c=64 ---------------------------
#pragma unroll 1
    for (int chunk = 0; chunk < 36; chunk++) {
        int s = chunk & 1, n = s ^ 1;
        int kc = chunk >> 2;
        uint32_t cur = sb + (uint32_t)s * STAGE_BYTES;
        uint32_t nxt = sb + (uint32_t)n * STAGE_BYTES;
        char* nxtp = smem + (size_t)n * STAGE_BYTES;

        bool produce = (chunk < 35);
        int kn = (chunk + 1) >> 2;
        int c0n = ((chunk + 1) & 3) << 6;
        int slotn = kn & 1;

        // samp for next tap (one tap ahead), off critical path
        if ((chunk & 3) == 0 && kc < 8)
            compute_samp(samp_w, samp_i, goffb, ho0, kc + 1, (kc + 1) & 1, tid);

        // async weight prefetch for chunk+1
        if (produce) {
            stage_weights_async(nxt, kn, c0n, tid);
            CP_COMMIT();
        }

        // 4 k16-steps: gather LDGs early, mma, combine+STS
#pragma unroll
        for (int ks = 0; ks < 4; ks++) {
            // --- gather loads for chunk+1 (1 item/thread/ks) ---
            float cr0[4][4], cr1[4][4];
            float4 wv; int4 iv;
            int p_g = 0, c8_g = 0;
            if (produce) {
                int e  = ks * 256 + tid;
                p_g  = e & 127;
                c8_g = e >> 7;
                wv = *(const float4*)(samp_w + slotn * 512 + p_g * 4);
                iv = *(const int4*)(samp_i + slotn * 512 + p_g * 4);
#pragma unroll
                for (int j = 0; j < 4; j++) {
                    const float* xp0 = xb + (size_t)(c0n + c8_g * 8 + j * 2) * HW_;
                    const float* xp1 = xp0 + HW_;
                    cr0[j][0] = xp0[iv.x]; cr0[j][1] = xp0[iv.y];
                    cr0[j][2] = xp0[iv.z]; cr0[j][3] = xp0[iv.w];
                    cr1[j][0] = xp1[iv.x]; cr1[j][1] = xp1[iv.y];
                    cr1[j][2] = xp1[iv.z]; cr1[j][3] = xp1[iv.w];
                }
            }

            // --- A fragments: 4 ldsm.x4 (o-tiles) ---
            uint32_t af[4][4];
#pragma unroll
            for (int mt = 0; mt < 4; mt++) {
                uint32_t byte = (uint32_t)((wo * 64 + mt * 16 + (mat & 1) * 8 + mr) * 128
                                           + ks * 32 + (mat >> 1) * 16);
                ldsm4(af[mt], cur + OFF_W + swz(byte));
            }
            // --- B fragments: 4 ldsm.x4 (each covers 2 n-tiles x k16) ---
            uint32_t bf[4][4];
#pragma unroll
            for (int nb = 0; nb < 4; nb++) {
                uint32_t byte = (uint32_t)((wp * 64 + nb * 16 + (mat >> 1) * 8 + mr) * 128
                                           + ks * 32 + (mat & 1) * 16);
                ldsm4(bf[nb], cur + OFF_P + swz(byte));
            }

            // --- 32 mmas, max accumulator reuse distance ---
#pragma unroll
            for (int nb = 0; nb < 4; nb++) {
#pragma unroll
                for (int half = 0; half < 2; half++) {
#pragma unroll
                    for (int mt = 0; mt < 4; mt++) {
                        mma_f16(acc[mt][2 * nb + half], af[mt], bf[nb] + 2 * half);
                    }
                }
            }

            // --- combine + cvt + STS into next stage P ---
            if (produce) {
                uint32_t hp[4];
#pragma unroll
                for (int j = 0; j < 4; j++) {
                    float v0 = wv.x * cr0[j][0] + wv.y * cr0[j][1]
                             + wv.z * cr0[j][2] + wv.w * cr0[j][3];
                    float v1 = wv.x * cr1[j][0] + wv.y * cr1[j][1]
                             + wv.z * cr1[j][2] + wv.w * cr1[j][3];
                    __half2 h2 = __floats2half2_rn(v0, v1);
                    hp[j] = *(uint32_t*)&h2;
                }
                uint32_t sw = swz((uint32_t)(p_g * 128 + c8_g * 16));
                *(uint4*)(nxtp + OFF_P + sw) = *(uint4*)hp;
            }
        }

        CP_WAIT0();
        __syncthreads();   // next stage staged; cur stage free
    }

    // ---------------- epilogue ----------------------------------------------
    int l4 = lane >> 2, l2 = (lane & 3) * 2;
#pragma unroll
    for (int mt = 0; mt < 4; mt++) {
#pragma unroll
        for (int nt = 0; nt < 8; nt++) {
            int o = wo * 64 + mt * 16 + l4;
            int p = wp * 64 + nt * 8 + l2;
            float* dst = g_y + ((size_t)(b * CO_ + o)) * HW_ + pos0 + p;
            *(float2*)dst = make_float2(acc[mt][nt][0], acc[mt][nt][1]);
            *(float2*)(dst + (size_t)8 * HW_) = make_float2(acc[mt][nt][2], acc[mt][nt][3]);
        }
    }
}

// ---------------------------------------------------------------------------
// Kernel 3: channel attention
// ---------------------------------------------------------------------------
__global__ void __launch_bounds__(256) attn_kernel(float* __restrict__ out) {
    int bo = blockIdx.x;
    const float4* yp = (const float4*)(g_y + (size_t)bo * HW_);
    int tid = threadIdx.x;

    float s = 0.f, s2 = 0.f;
    float4 v[4];
#pragma unroll
    for (int i = 0; i < 4; i++) {
        v[i] = yp[tid + i * 256];
        s  += v[i].x + v[i].y + v[i].z + v[i].w;
        s2 += v[i].x * v[i].x + v[i].y * v[i].y + v[i].z * v[i].z + v[i].w * v[i].w;
    }
#pragma unroll
    for (int off = 16; off; off >>= 1) {
        s  += __shfl_down_sync(0xffffffffu, s,  off);
        s2 += __shfl_down_sync(0xffffffffu, s2, off);
    }
    __shared__ float rs[8], rs2[8];
    __shared__ float sa;
    int lane = tid & 31, w = tid >> 5;
    if (lane == 0) { rs[w] = s; rs2[w] = s2; }
    __syncthreads();
    if (tid == 0) {
        float S = 0.f, S2 = 0.f;
#pragma unroll
        for (int i = 0; i < 8; i++) { S += rs[i]; S2 += rs2[i]; }
        float mean = S * (1.f / 4096.f);
        float var  = (S2 - S * S * (1.f / 4096.f)) * (1.f / 4095.f);
        float sd   = sqrtf(fmaxf(var, 0.f));
        sa = 1.f / (1.f + expf(-(mean + sd)));
    }
    __syncthreads();
    float a = sa;
    float4* op = (float4*)(out + (size_t)bo * HW_);
#pragma unroll
    for (int i = 0; i < 4; i++) {
        float4 u = v[i];
        u.x *= a; u.y *= a; u.z *= a; u.w *= a;
        op[tid + i * 256] = u;
    }
}

// ---------------------------------------------------------------------------
extern "C" void kernel_launch(void* const* d_in, const int* in_sizes, int n_in,
                              void* d_out, int out_size) {
    const float* x  = (const float*)d_in[0];   // [8,256,64,64]
    const float* ow = (const float*)d_in[1];   // [18,256,3,3]
    const float* dw = (const float*)d_in[2];   // [256,256,3,3]
    float* out = (float*)d_out;                // [8,256,64,64]

    cudaFuncSetAttribute(deform_mma_kernel,
                         cudaFuncAttributeMaxDynamicSharedMemorySize, SMEM_TOTAL);

    wt_prep_kernel<<<(K_ * CO_ * C_) / 256, 256>>>(dw);
    offset_conv_kernel<<<(B_ * HW_) / 256, 256>>>(x, ow);
    deform_mma_kernel<<<B_ * 32, 256, SMEM_TOTAL>>>(x);
    attn_kernel<<<B_ * CO_, 256>>>(out);
}